// round 3
// baseline (speedup 1.0000x reference)
#include <cuda_runtime.h>

#define N_NODES_MAX 100000
#define N_EDGES_MAX 1600000
#define HID 128
#define VOCAB 28
#define N_GRAPHS 2048

// ---- scratch (device globals; no allocation allowed) ----
__device__ int   g_cnt[N_NODES_MAX * VOCAB];   // per-node atom-type histogram (11.2 MB)
__device__ float g_T1[VOCAB * HID];            // embed @ w1_0
__device__ float g_Ep[VOCAB * HID];            // embed @ (w1_0 @ w2_0)
__device__ float g_b0c[HID];                   // b1_0 @ w2_0 + b2_0
__device__ float g_Wc[HID];                    // w1_1 @ w2_1
__device__ float g_scal[3];                    // {1+eps0, 1+eps1, bc}
__device__ float g_z1[N_NODES_MAX];            // relu(h0) . Wc  per node
__device__ float g_xacc[N_NODES_MAX];          // layer-1 scalar aggregation
__device__ float g_ydummy[N_GRAPHS];           // fallback sink

// ---- zero scratch + output y-region ----
__global__ void k_zero(float* y_out, int y_len, int n_nodes) {
    int stride = gridDim.x * blockDim.x;
    int i = blockIdx.x * blockDim.x + threadIdx.x;
    int total = n_nodes * VOCAB;
    for (int idx = i; idx < total; idx += stride) g_cnt[idx] = 0;
    for (int idx = i; idx < n_nodes; idx += stride) g_xacc[idx] = 0.f;
    for (int idx = i; idx < y_len; idx += stride) y_out[idx] = 0.f;
}

// ---- prep: T1 = embed@w1_0 ; b0c ; Wc ; scalars ----
__global__ void k_prep1(const float* __restrict__ embed, const float* __restrict__ w1_0,
                        const float* __restrict__ b1_0, const float* __restrict__ w2_0,
                        const float* __restrict__ b2_0,
                        const float* __restrict__ w1_1, const float* __restrict__ w2_1,
                        const float* __restrict__ b1_1, const float* __restrict__ b2_1,
                        const float* __restrict__ eps0, const float* __restrict__ eps1) {
    int b = blockIdx.x, j = threadIdx.x;
    if (b < VOCAB) {
        float acc = 0.f;
        #pragma unroll 8
        for (int m = 0; m < HID; m++) acc = fmaf(embed[b * HID + m], w1_0[m * HID + j], acc);
        g_T1[b * HID + j] = acc;
    } else if (b == VOCAB) {                  // b0c[j] = sum_k b1_0[k]*w2_0[k][j] + b2_0[j]
        float acc = b2_0[j];
        #pragma unroll 8
        for (int k = 0; k < HID; k++) acc = fmaf(b1_0[k], w2_0[k * HID + j], acc);
        g_b0c[j] = acc;
    } else if (b == VOCAB + 1) {              // Wc[k] = sum_j w1_1[k][j]*w2_1[j]
        float acc = 0.f;
        #pragma unroll 8
        for (int jj = 0; jj < HID; jj++) acc = fmaf(w1_1[j * HID + jj], w2_1[jj], acc);
        g_Wc[j] = acc;
    } else if (j == 0) {
        float bc = b2_1[0];
        for (int jj = 0; jj < HID; jj++) bc = fmaf(b1_1[jj], w2_1[jj], bc);
        g_scal[0] = 1.f + eps0[0];
        g_scal[1] = 1.f + eps1[0];
        g_scal[2] = bc;
    }
}

// ---- prep2: Ep = T1 @ w2_0 ----
__global__ void k_prep2(const float* __restrict__ w2_0) {
    int t = blockIdx.x, j = threadIdx.x;
    float acc = 0.f;
    #pragma unroll 8
    for (int k = 0; k < HID; k++) acc = fmaf(g_T1[t * HID + k], w2_0[k * HID + j], acc);
    g_P:
    g_Ep[t * HID + j] = acc;
}

// ---- edge histogram: cnt[dst][type(src)]++ ----
__global__ void k_hist(const int* __restrict__ src, const int* __restrict__ dst,
                       const int* __restrict__ xidx, int n_edges) {
    int e = blockIdx.x * blockDim.x + threadIdx.x;
    if (e < n_edges) {
        int t = xidx[src[e]];
        atomicAdd(&g_cnt[dst[e] * VOCAB + t], 1);
    }
}

// ---- fused layer0 + z1: one warp per node ----
__global__ void __launch_bounds__(1024)
k_node(const int* __restrict__ xidx, int n_nodes) {
    __shared__ __align__(16) float sEp[VOCAB * HID];
    __shared__ __align__(16) float sB[HID];
    __shared__ __align__(16) float sW[HID];
    int tid = threadIdx.x;
    for (int i = tid; i < VOCAB * HID; i += blockDim.x) sEp[i] = g_Ep[i];
    if (tid < HID) { sB[tid] = g_b0c[tid]; sW[tid] = g_Wc[tid]; }
    __syncthreads();

    float eps0p = g_scal[0];
    int warp = tid >> 5, lane = tid & 31;
    int node = blockIdx.x * (blockDim.x >> 5) + warp;
    if (node >= n_nodes) return;

    int c = 0;
    if (lane < VOCAB) c = g_cnt[node * VOCAB + lane];
    int tn = xidx[node];
    int j0 = lane * 4;

    float4 acc = *(const float4*)(&sB[j0]);
    {
        float4 e4 = *(const float4*)(&sEp[tn * HID + j0]);
        acc.x = fmaf(eps0p, e4.x, acc.x); acc.y = fmaf(eps0p, e4.y, acc.y);
        acc.z = fmaf(eps0p, e4.z, acc.z); acc.w = fmaf(eps0p, e4.w, acc.w);
    }
    #pragma unroll
    for (int t = 0; t < VOCAB; t++) {
        int ct = __shfl_sync(0xffffffffu, c, t);
        if (ct) {
            float f = (float)ct;
            float4 e4 = *(const float4*)(&sEp[t * HID + j0]);
            acc.x = fmaf(f, e4.x, acc.x); acc.y = fmaf(f, e4.y, acc.y);
            acc.z = fmaf(f, e4.z, acc.z); acc.w = fmaf(f, e4.w, acc.w);
        }
    }
    // relu, dot with Wc, warp-reduce
    float4 w4 = *(const float4*)(&sW[j0]);
    float s = fmaxf(acc.x, 0.f) * w4.x + fmaxf(acc.y, 0.f) * w4.y
            + fmaxf(acc.z, 0.f) * w4.z + fmaxf(acc.w, 0.f) * w4.w;
    #pragma unroll
    for (int o = 16; o > 0; o >>= 1) s += __shfl_xor_sync(0xffffffffu, s, o);
    if (lane == 0) g_z1[node] = s;
}

// ---- layer1 scalar scatter: xacc[dst] += z1[src] ----
__global__ void k_scatter(const int* __restrict__ src, const int* __restrict__ dst, int n_edges) {
    int e = blockIdx.x * blockDim.x + threadIdx.x;
    if (e < n_edges) atomicAdd(&g_xacc[dst[e]], g_z1[src[e]]);
}

// ---- finalize: x_out + graph readout (batch sorted -> warp-segmented reduce) ----
__global__ void k_final(const int* __restrict__ batch, float* __restrict__ y_out,
                        float* __restrict__ x_out, int n_nodes) {
    int n = blockIdx.x * blockDim.x + threadIdx.x;
    float eps1p = g_scal[1], bc = g_scal[2];
    float v = 0.f;
    int g = -1;
    if (n < n_nodes) {
        v = g_xacc[n] + fmaf(eps1p, g_z1[n], bc);
        x_out[n] = v;
        g = batch[n];
    }
    int lane = threadIdx.x & 31;
    // inclusive segmented scan over sorted segment ids
    #pragma unroll
    for (int d = 1; d < 32; d <<= 1) {
        float up = __shfl_up_sync(0xffffffffu, v, d);
        int gu = __shfl_up_sync(0xffffffffu, g, d);
        if (lane >= d && gu == g) v += up;
    }
    int gd = __shfl_down_sync(0xffffffffu, g, 1);
    bool last = (lane == 31) || (gd != g);
    if (n < n_nodes && last) atomicAdd(&y_out[g], v);
}

extern "C" void kernel_launch(void* const* d_in, const int* in_sizes, int n_in,
                              void* d_out, int out_size) {
    const int*   x_idx    = (const int*)d_in[0];
    const int*   edge_src = (const int*)d_in[1];
    const int*   edge_dst = (const int*)d_in[2];
    const int*   batch    = (const int*)d_in[3];
    const float* embed    = (const float*)d_in[4];
    const float* eps0     = (const float*)d_in[5];
    const float* w1_0     = (const float*)d_in[6];
    const float* b1_0     = (const float*)d_in[7];
    const float* w2_0     = (const float*)d_in[8];
    const float* b2_0     = (const float*)d_in[9];
    const float* eps1     = (const float*)d_in[10];
    const float* w1_1     = (const float*)d_in[11];
    const float* b1_1     = (const float*)d_in[12];
    const float* w2_1     = (const float*)d_in[13];
    const float* b2_1     = (const float*)d_in[14];

    int n_nodes = in_sizes[0];
    int n_edges = in_sizes[1];
    if (n_nodes > N_NODES_MAX) n_nodes = N_NODES_MAX;
    if (n_edges > N_EDGES_MAX) n_edges = N_EDGES_MAX;

    float* out = (float*)d_out;
    float* y_out;
    float* x_out;
    int y_len;
    if (out_size >= n_nodes + 1) {           // (y_hat, x) concatenated, y first
        y_len = out_size - n_nodes;
        y_out = out;
        x_out = out + y_len;
    } else {                                  // only y_hat
        y_len = out_size;
        y_out = out;
        x_out = g_xacc;                       // discard (safe: per-thread read-before-write)
    }

    k_zero<<<1024, 256>>>(y_out, y_len, n_nodes);
    k_prep1<<<VOCAB + 3, HID>>>(embed, w1_0, b1_0, w2_0, b2_0,
                                w1_1, w2_1, b1_1, b2_1, eps0, eps1);
    k_prep2<<<VOCAB, HID>>>(w2_0);
    k_hist<<<(n_edges + 255) / 256, 256>>>(edge_src, edge_dst, x_idx, n_edges);
    k_node<<<(n_nodes + 31) / 32, 1024>>>(x_idx, n_nodes);
    k_scatter<<<(n_edges + 255) / 256, 256>>>(edge_src, edge_dst, n_edges);
    k_final<<<(n_nodes + 255) / 256, 256>>>(batch, y_out, x_out, n_nodes);
}

// round 5
// speedup vs baseline: 1.2402x; 1.2402x over previous
#include <cuda_runtime.h>

#define HID 128
#define VOCAB 28
#define N_NODES_MAX 100000
#define N_EDGES_MAX 1600000

// ---- device scratch (no allocations allowed) ----
// Packed per-node histogram: 8 uint32 per node = 28 byte-counters + pad = one 32B sector.
__device__ __align__(16) unsigned g_cntp[N_NODES_MAX * 8];   // 3.2 MB
__device__ float g_Ep[VOCAB * HID];     // embed @ (w1_0 @ w2_0)
__device__ float g_b0c[HID];            // b1_0 @ w2_0 + b2_0
__device__ float g_Wc[HID];             // w1_1 @ w2_1
__device__ float g_scal[3];             // {1+eps0, 1+eps1, b1_1.w2_1 + b2_1}
__device__ float g_z1[N_NODES_MAX];     // relu(h0) . Wc  per node
__device__ float g_xfall[N_NODES_MAX];  // fallback x buffer if output has no x region

// ---- one init kernel: folded weights + scalars + zero hist + zero y ----
__global__ void __launch_bounds__(128)
k_init(const float* __restrict__ embed, const float* __restrict__ w1_0,
       const float* __restrict__ b1_0,  const float* __restrict__ w2_0,
       const float* __restrict__ b2_0,  const float* __restrict__ w1_1,
       const float* __restrict__ b1_1,  const float* __restrict__ w2_1,
       const float* __restrict__ b2_1,  const float* __restrict__ eps0,
       const float* __restrict__ eps1,
       float* __restrict__ y_out, int y_len, int n_nodes) {
    int b = blockIdx.x, j = threadIdx.x;
    if (b < VOCAB) {
        // Ep[b][:] : row b of embed@w1_0 (to smem), then @w2_0
        __shared__ float sT[HID];
        float acc = 0.f;
        #pragma unroll 8
        for (int m = 0; m < HID; m++) acc = fmaf(embed[b * HID + m], w1_0[m * HID + j], acc);
        sT[j] = acc;
        __syncthreads();
        float acc2 = 0.f;
        #pragma unroll 8
        for (int k = 0; k < HID; k++) acc2 = fmaf(sT[k], w2_0[k * HID + j], acc2);
        g_Ep[b * HID + j] = acc2;
    } else if (b == VOCAB) {            // b0c = b1_0 @ w2_0 + b2_0
        float acc = b2_0[j];
        #pragma unroll 8
        for (int k = 0; k < HID; k++) acc = fmaf(b1_0[k], w2_0[k * HID + j], acc);
        g_b0c[j] = acc;
    } else if (b == VOCAB + 1) {        // Wc = w1_1 @ w2_1
        float acc = 0.f;
        #pragma unroll 8
        for (int jj = 0; jj < HID; jj++) acc = fmaf(w1_1[j * HID + jj], w2_1[jj], acc);
        g_Wc[j] = acc;
    } else if (b == VOCAB + 2) {        // scalars + zero y_out
        if (j == 0) {
            float bc = b2_1[0];
            for (int jj = 0; jj < HID; jj++) bc = fmaf(b1_1[jj], w2_1[jj], bc);
            g_scal[0] = 1.f + eps0[0];
            g_scal[1] = 1.f + eps1[0];
            g_scal[2] = bc;
        }
        for (int i = j; i < y_len; i += 128) y_out[i] = 0.f;
    } else {                            // zero g_cntp (uint4 stores)
        uint4* p = (uint4*)g_cntp;
        int nq = n_nodes * 2;           // 8 words = 2 uint4 per node
        int idx = (b - (VOCAB + 3)) * 128 + j;
        int stride = (gridDim.x - (VOCAB + 3)) * 128;
        uint4 z = make_uint4(0u, 0u, 0u, 0u);
        for (int i = idx; i < nq; i += stride) p[i] = z;
    }
}

// ---- edge histogram (×4 vectorized, packed byte counters) ----
__global__ void __launch_bounds__(256)
k_hist(const int* __restrict__ src, const int* __restrict__ dst,
       const int* __restrict__ xidx, int n4, int n_rem, int base) {
    int i = blockIdx.x * blockDim.x + threadIdx.x;
    if (i < n4) {
        int4 s = ((const int4*)src)[i];
        int4 d = ((const int4*)dst)[i];
        int t0 = xidx[s.x], t1 = xidx[s.y], t2 = xidx[s.z], t3 = xidx[s.w];
        atomicAdd(&g_cntp[d.x * 8 + (t0 >> 2)], 1u << ((t0 & 3) * 8));
        atomicAdd(&g_cntp[d.y * 8 + (t1 >> 2)], 1u << ((t1 & 3) * 8));
        atomicAdd(&g_cntp[d.z * 8 + (t2 >> 2)], 1u << ((t2 & 3) * 8));
        atomicAdd(&g_cntp[d.w * 8 + (t3 >> 2)], 1u << ((t3 & 3) * 8));
    }
    if (i < n_rem) {
        int e = base + i;
        int t = xidx[src[e]];
        atomicAdd(&g_cntp[dst[e] * 8 + (t >> 2)], 1u << ((t & 3) * 8));
    }
}

// ---- fused layer0 + z1 + x_out init: one warp per node, grid-stride ----
__global__ void __launch_bounds__(256)
k_node(const int* __restrict__ xidx, float* __restrict__ x_out, int n_nodes) {
    __shared__ __align__(16) float sEp[VOCAB * HID];
    __shared__ __align__(16) float sB[HID];
    __shared__ __align__(16) float sW[HID];
    int tid = threadIdx.x;
    for (int i = tid; i < VOCAB * HID; i += 256) sEp[i] = g_Ep[i];
    if (tid < HID) { sB[tid] = g_b0c[tid]; sW[tid] = g_Wc[tid]; }
    __syncthreads();

    float eps0p = g_scal[0], eps1p = g_scal[1], bc = g_scal[2];
    int lane = tid & 31;
    int j0 = lane * 4;
    float4 w4 = *(const float4*)&sW[j0];
    float4 b4 = *(const float4*)&sB[j0];
    int wglob = blockIdx.x * 8 + (tid >> 5);
    int wstride = gridDim.x * 8;

    for (int node = wglob; node < n_nodes; node += wstride) {
        unsigned w = 0;
        if (lane < 8) w = g_cntp[node * 8 + lane];   // one sector per node
        int tn = xidx[node];
        float4 acc = b4;
        {
            float4 e4 = *(const float4*)&sEp[tn * HID + j0];
            acc.x = fmaf(eps0p, e4.x, acc.x); acc.y = fmaf(eps0p, e4.y, acc.y);
            acc.z = fmaf(eps0p, e4.z, acc.z); acc.w = fmaf(eps0p, e4.w, acc.w);
        }
        #pragma unroll
        for (int t = 0; t < VOCAB; t++) {
            unsigned wt = __shfl_sync(0xffffffffu, w, t >> 2);
            unsigned ct = (wt >> ((t & 3) * 8)) & 255u;
            if (ct) {                                  // uniform across warp: no divergence
                float f = (float)ct;
                float4 e4 = *(const float4*)&sEp[t * HID + j0];
                acc.x = fmaf(f, e4.x, acc.x); acc.y = fmaf(f, e4.y, acc.y);
                acc.z = fmaf(f, e4.z, acc.z); acc.w = fmaf(f, e4.w, acc.w);
            }
        }
        float s = fmaxf(acc.x, 0.f) * w4.x + fmaxf(acc.y, 0.f) * w4.y
                + fmaxf(acc.z, 0.f) * w4.z + fmaxf(acc.w, 0.f) * w4.w;
        #pragma unroll
        for (int o = 16; o > 0; o >>= 1) s += __shfl_xor_sync(0xffffffffu, s, o);
        if (lane == 0) {
            g_z1[node] = s;
            x_out[node] = fmaf(eps1p, s, bc);   // (1+eps1)*z1 + bias; scatter adds on top
        }
    }
}

// ---- layer1 scalar scatter straight into x_out (×4 vectorized) ----
__global__ void __launch_bounds__(256)
k_scatter(const int* __restrict__ src, const int* __restrict__ dst,
          float* __restrict__ x_out, int n4, int n_rem, int base) {
    int i = blockIdx.x * blockDim.x + threadIdx.x;
    if (i < n4) {
        int4 s = ((const int4*)src)[i];
        int4 d = ((const int4*)dst)[i];
        float z0 = g_z1[s.x], z1v = g_z1[s.y], z2 = g_z1[s.z], z3 = g_z1[s.w];
        atomicAdd(&x_out[d.x], z0);
        atomicAdd(&x_out[d.y], z1v);
        atomicAdd(&x_out[d.z], z2);
        atomicAdd(&x_out[d.w], z3);
    }
    if (i < n_rem) {
        int e = base + i;
        atomicAdd(&x_out[dst[e]], g_z1[src[e]]);
    }
}

// ---- graph readout: sorted batch -> warp-segmented reduce ----
__global__ void __launch_bounds__(256)
k_final(const int* __restrict__ batch, const float* __restrict__ x_out,
        float* __restrict__ y_out, int n_nodes) {
    int n = blockIdx.x * blockDim.x + threadIdx.x;
    float v = 0.f;
    int g = -1;
    if (n < n_nodes) { v = x_out[n]; g = batch[n]; }
    int lane = threadIdx.x & 31;
    #pragma unroll
    for (int d = 1; d < 32; d <<= 1) {
        float up = __shfl_up_sync(0xffffffffu, v, d);
        int gu = __shfl_up_sync(0xffffffffu, g, d);
        if (lane >= d && gu == g) v += up;
    }
    int gd = __shfl_down_sync(0xffffffffu, g, 1);
    bool last = (lane == 31) || (gd != g);
    if (n < n_nodes && last) atomicAdd(&y_out[g], v);
}

extern "C" void kernel_launch(void* const* d_in, const int* in_sizes, int n_in,
                              void* d_out, int out_size) {
    const int*   x_idx    = (const int*)d_in[0];
    const int*   edge_src = (const int*)d_in[1];
    const int*   edge_dst = (const int*)d_in[2];
    const int*   batch    = (const int*)d_in[3];
    const float* embed    = (const float*)d_in[4];
    const float* eps0     = (const float*)d_in[5];
    const float* w1_0     = (const float*)d_in[6];
    const float* b1_0     = (const float*)d_in[7];
    const float* w2_0     = (const float*)d_in[8];
    const float* b2_0     = (const float*)d_in[9];
    const float* eps1     = (const float*)d_in[10];
    const float* w1_1     = (const float*)d_in[11];
    const float* b1_1     = (const float*)d_in[12];
    const float* w2_1     = (const float*)d_in[13];
    const float* b2_1     = (const float*)d_in[14];

    int n_nodes = in_sizes[0];
    int n_edges = in_sizes[1];
    if (n_nodes > N_NODES_MAX) n_nodes = N_NODES_MAX;
    if (n_edges > N_EDGES_MAX) n_edges = N_EDGES_MAX;

    float* out = (float*)d_out;
    float* y_out;
    float* x_out;
    int y_len;
    if (out_size >= n_nodes + 1) {     // (y_hat, x) concatenated, y first
        y_len = out_size - n_nodes;
        y_out = out;
        x_out = out + y_len;
    } else {
        y_len = out_size;
        y_out = out;
        x_out = g_xfall;
    }

    int n4   = n_edges >> 2;
    int base = n4 << 2;
    int rem  = n_edges - base;

    k_init<<<VOCAB + 3 + 1536, 128>>>(embed, w1_0, b1_0, w2_0, b2_0,
                                      w1_1, b1_1, w2_1, b2_1, eps0, eps1,
                                      y_out, y_len, n_nodes);
    k_hist<<<(n4 + 255) / 256, 256>>>(edge_src, edge_dst, x_idx, n4, rem, base);
    k_node<<<592, 256>>>(x_idx, x_out, n_nodes);
    k_scatter<<<(n4 + 255) / 256, 256>>>(edge_src, edge_dst, x_out, n4, rem, base);
    k_final<<<(n_nodes + 255) / 256, 256>>>(batch, x_out, y_out, n_nodes);
}